// round 13
// baseline (speedup 1.0000x reference)
#include <cuda_runtime.h>
#include <cstdint>

#define NN 50000
#define NE 400000
#define ET (NN + NE)
#define NEG_SLOPE 0.2f

// ---------------- scratch (device globals) -----------------------------------
__device__ float g_xl[NN * 256];
__device__ float g_xr[NN * 256];
__device__ float g_hA[NN * 256];
__device__ float g_hB[NN * 256];
__device__ int   g_cnt[NN];
__device__ int   g_ofs[NN];
__device__ int   g_fill[NN];
__device__ int   g_srcList[ET];
__device__ int   g_bsum[256];
__device__ int   g_boff[256];
__device__ int   g_is64;

// ---------------- helpers ----------------------------------------------------
__device__ __forceinline__ const float* selIn(const float* ext, int sel) {
    return sel == 1 ? g_hA : (sel == 2 ? g_hB : ext);
}
__device__ __forceinline__ float* selOut(float* ext, int sel) {
    return sel == 1 ? g_hA : (sel == 2 ? g_hB : ext);
}

// f32 -> tf32 (rna) in register
__device__ __forceinline__ unsigned t32(float f) {
    unsigned u;
    asm("cvt.rna.tf32.f32 %0, %1;" : "=r"(u) : "f"(f));
    return u;
}

__device__ __forceinline__ void cpasync16(const void* smem_dst, const void* gsrc, int sz) {
    unsigned dst = (unsigned)__cvta_generic_to_shared(smem_dst);
    asm volatile("cp.async.cg.shared.global [%0], [%1], 16, %2;"
                 :: "r"(dst), "l"(gsrc), "r"(sz));
}
#define CP_COMMIT() asm volatile("cp.async.commit_group;")
#define CP_WAIT1()  asm volatile("cp.async.wait_group 1;")

// merged: zero g_cnt across grid; block 0 also detects edge_index dtype
__global__ void init_csr_kernel(const int* __restrict__ ei) {
    int i = blockIdx.x * blockDim.x + threadIdx.x;
    if (i < NN) g_cnt[i] = 0;
    if (blockIdx.x == 0 && threadIdx.x == 0) {
        int all0 = 1;
        for (int j = 0; j < 64; j++)
            if (ei[2 * j + 1] != 0) all0 = 0;
        g_is64 = all0;
    }
}

__device__ __forceinline__ void load_edge(const void* ei, int e, int& s, int& d) {
    if (e >= NE) { s = d = e - NE; return; }   // self loops appended at the end
    if (g_is64) {
        const long long* p = (const long long*)ei;
        s = (int)p[e]; d = (int)p[NE + e];
    } else {
        const int* p = (const int*)ei;
        s = p[e]; d = p[NE + e];
    }
}

// ---------------- CSR build ---------------------------------------------------
__global__ void count_kernel(const void* ei) {
    int e = blockIdx.x * blockDim.x + threadIdx.x;
    if (e >= ET) return;
    int s, d; load_edge(ei, e, s, d);
    (void)s;
    atomicAdd(&g_cnt[d], 1);
}

__global__ void scan1_kernel() {
    __shared__ int ws[8];
    int tid = threadIdx.x, lane = tid & 31, wid = tid >> 5;
    int i = blockIdx.x * 256 + tid;
    int v = (i < NN) ? g_cnt[i] : 0;
    int x = v;
#pragma unroll
    for (int o = 1; o < 32; o <<= 1) {
        int y = __shfl_up_sync(0xffffffffu, x, o);
        if (lane >= o) x += y;
    }
    if (lane == 31) ws[wid] = x;
    __syncthreads();
    if (tid == 0) {
        int run = 0;
        for (int j = 0; j < 8; j++) { int t = ws[j]; ws[j] = run; run += t; }
        g_bsum[blockIdx.x] = run;
    }
    __syncthreads();
    if (i < NN) g_ofs[i] = x - v + ws[wid];
}

__global__ void scan2_kernel(int nb) {
    __shared__ int ws[8];
    int tid = threadIdx.x, lane = tid & 31, wid = tid >> 5;
    int v = (tid < nb) ? g_bsum[tid] : 0;
    int x = v;
#pragma unroll
    for (int o = 1; o < 32; o <<= 1) {
        int y = __shfl_up_sync(0xffffffffu, x, o);
        if (lane >= o) x += y;
    }
    if (lane == 31) ws[wid] = x;
    __syncthreads();
    if (tid == 0) {
        int run = 0;
        for (int j = 0; j < 8; j++) { int t = ws[j]; ws[j] = run; run += t; }
    }
    __syncthreads();
    if (tid < nb) g_boff[tid] = x - v + ws[wid];
}

__global__ void scan3_kernel() {
    int i = blockIdx.x * 256 + threadIdx.x;
    if (i >= NN) return;
    int o = g_ofs[i] + g_boff[blockIdx.x];
    g_ofs[i] = o;
    g_fill[i] = o;
}

__global__ void fill_kernel(const void* ei) {
    int e = blockIdx.x * blockDim.x + threadIdx.x;
    if (e >= ET) return;
    int s, d; load_edge(ei, e, s, d);
    int pos = atomicAdd(&g_fill[d], 1);
    g_srcList[pos] = s;
}

// ---------------- tf32 tensor-core GEMM, 512 threads / 16 warps --------------
// [xl | xr] = A[M,K] @ [Wl | Wr], block 128x128, K-step 16, 2 stages.
// 16 warps in a 4m x 4n grid, warp tile 32x32 (2x4 MMAs, acc = 32 regs/thread).
// Same data movement as R6; finer warp granularity doubles resident warps.
#define MMA_TF32(d, a, b)                                                      \
    asm volatile(                                                              \
        "mma.sync.aligned.m16n8k8.row.col.f32.tf32.tf32.f32 "                  \
        "{%0,%1,%2,%3}, {%4,%5,%6,%7}, {%8,%9}, {%0,%1,%2,%3};"                \
        : "+f"(d[0]), "+f"(d[1]), "+f"(d[2]), "+f"(d[3])                       \
        : "r"(a[0]), "r"(a[1]), "r"(a[2]), "r"(a[3]), "r"(b[0]), "r"(b[1]))

__global__ __launch_bounds__(512, 2) void gemm_tf32(
    const float* __restrict__ Aext, int asel,
    const float* __restrict__ Wl, const float* __restrict__ Wr,
    int M, int HC, int fusedN, int K)
{
    __shared__ float As[2][128][20];   // 128 rows x 16 k
    __shared__ float Bs[2][16][132];   // 16 k x 128 cols

    const float* A = selIn(Aext, asel);

    int tid = threadIdx.x;
    int lane = tid & 31, warp = tid >> 5;
    int wm = (warp & 3) * 32, wn = (warp >> 2) * 32;
    int rowBase = blockIdx.y * 128, colBase = blockIdx.x * 128;

    float acc[2][4][4];
#pragma unroll
    for (int i = 0; i < 2; i++)
#pragma unroll
        for (int j = 0; j < 4; j++)
#pragma unroll
            for (int q = 0; q < 4; q++) acc[i][j][q] = 0.f;

    // loaders: 512 threads, one 16B cp.async each for A and for B
    int aRow0 = tid >> 2, aCol = (tid & 3) * 4;     // A: 128 rows x 16 k
    int bRow0 = tid >> 5, bCol = (tid & 31) * 4;    // B: 16 k x 128 cols

    int gc = colBase + bCol;
    const float* bColBase_ptr;
    int bsz;
    if (gc >= fusedN) { bColBase_ptr = Wl; bsz = 0; }
    else if (gc < HC) { bColBase_ptr = Wl + gc; bsz = 16; }
    else              { bColBase_ptr = Wr + (gc - HC); bsz = 16; }

    int gr0 = rowBase + aRow0;
    const float* aPtr0 = A + (size_t)min(gr0, M - 1) * K + aCol;
    int asz0 = (gr0 < M) ? 16 : 0;

    int nK = K >> 4;

#define ISSUE(kt, buf)                                                          \
    do {                                                                        \
        int k0_ = (kt) << 4;                                                    \
        cpasync16(&As[buf][aRow0][aCol], aPtr0 + k0_, asz0);                    \
        cpasync16(&Bs[buf][bRow0][bCol],                                        \
                  bColBase_ptr + (size_t)(k0_ + bRow0) * HC, bsz);              \
    } while (0)

    ISSUE(0, 0);
    CP_COMMIT();

    int buf = 0;
    int r = lane >> 2, c = lane & 3;

    for (int kt = 0; kt < nK; kt++) {
        if (kt + 1 < nK) ISSUE(kt + 1, buf ^ 1);
        CP_COMMIT();
        CP_WAIT1();
        __syncthreads();

#pragma unroll
        for (int ks = 0; ks < 2; ks++) {
            int kk = ks * 8;
            unsigned a[2][4], b[4][2];
#pragma unroll
            for (int mi = 0; mi < 2; mi++) {
                int rb = wm + mi * 16 + r;
                a[mi][0] = t32(As[buf][rb][kk + c]);
                a[mi][1] = t32(As[buf][rb + 8][kk + c]);
                a[mi][2] = t32(As[buf][rb][kk + c + 4]);
                a[mi][3] = t32(As[buf][rb + 8][kk + c + 4]);
            }
#pragma unroll
            for (int ni = 0; ni < 4; ni++) {
                int nb = wn + ni * 8 + r;
                b[ni][0] = t32(Bs[buf][kk + c][nb]);
                b[ni][1] = t32(Bs[buf][kk + c + 4][nb]);
            }
#pragma unroll
            for (int mi = 0; mi < 2; mi++)
#pragma unroll
                for (int ni = 0; ni < 4; ni++)
                    MMA_TF32(acc[mi][ni], a[mi], b[ni]);
        }
        __syncthreads();
        buf ^= 1;
    }
#undef ISSUE

    // ---- epilogue: route columns to g_xl / g_xr
    int c2 = (lane & 3) * 2;
#pragma unroll
    for (int mi = 0; mi < 2; mi++) {
#pragma unroll
        for (int ni = 0; ni < 4; ni++) {
            int col = colBase + wn + ni * 8 + c2;
            if (col >= fusedN) continue;
            float* base; int cc;
            if (col < HC) { base = g_xl; cc = col; }
            else          { base = g_xr; cc = col - HC; }
#pragma unroll
            for (int half = 0; half < 2; half++) {
                int row = rowBase + wm + mi * 16 + r + half * 8;
                if (row < M) {
                    *(float2*)(base + (size_t)row * HC + cc) =
                        make_float2(acc[mi][ni][half * 2],
                                    acc[mi][ni][half * 2 + 1]);
                }
            }
        }
    }
}

// ---------------- fused aggregation, H=2 C=128, head-split lanes (R6) --------
__global__ __launch_bounds__(256) void gat_agg2_kernel(
    const float* __restrict__ att, const float* __restrict__ bias,
    float* outext, int osel)
{
    constexpr int HC = 256;
    int nd = (blockIdx.x * blockDim.x + threadIdx.x) >> 5;
    int lane = threadIdx.x & 31;
    if (nd >= NN) return;

    int colBase = (lane >> 4) * 128 + (lane & 15) * 8;

    float xr8[8], at8[8], acc8[8];
    {
        const float* xrp = g_xr + (size_t)nd * HC + colBase;
        const float* atp = att + colBase;
        float4 xa = *(const float4*)(xrp), xb = *(const float4*)(xrp + 4);
        float4 aa = *(const float4*)(atp), ab = *(const float4*)(atp + 4);
        xr8[0]=xa.x; xr8[1]=xa.y; xr8[2]=xa.z; xr8[3]=xa.w;
        xr8[4]=xb.x; xr8[5]=xb.y; xr8[6]=xb.z; xr8[7]=xb.w;
        at8[0]=aa.x; at8[1]=aa.y; at8[2]=aa.z; at8[3]=aa.w;
        at8[4]=ab.x; at8[5]=ab.y; at8[6]=ab.z; at8[7]=ab.w;
#pragma unroll
        for (int j = 0; j < 8; j++) acc8[j] = 0.f;
    }
    float m = -1e30f, den = 0.f;

    int beg = g_ofs[nd];
    int end = (nd == NN - 1) ? ET : g_ofs[nd + 1];
    int i = beg;
    int endPair = beg + ((end - beg) & ~1);

    for (; i < endPair; i += 2) {
        int s0 = g_srcList[i];
        int s1 = g_srcList[i + 1];
        const float* p0 = g_xl + (size_t)s0 * HC + colBase;
        const float* p1 = g_xl + (size_t)s1 * HC + colBase;

        float4 u0 = *(const float4*)(p0), u1 = *(const float4*)(p0 + 4);
        float4 v0 = *(const float4*)(p1), v1 = *(const float4*)(p1 + 4);
        float xv0[8] = {u0.x,u0.y,u0.z,u0.w,u1.x,u1.y,u1.z,u1.w};
        float xv1[8] = {v0.x,v0.y,v0.z,v0.w,v1.x,v1.y,v1.z,v1.w};

        float d0 = 0.f, d1 = 0.f;
#pragma unroll
        for (int j = 0; j < 8; j++) {
            float e0 = xv0[j] + xr8[j];
            float e1 = xv1[j] + xr8[j];
            e0 = (e0 > 0.f) ? e0 : NEG_SLOPE * e0;
            e1 = (e1 > 0.f) ? e1 : NEG_SLOPE * e1;
            d0 += e0 * at8[j];
            d1 += e1 * at8[j];
        }
#pragma unroll
        for (int o = 8; o; o >>= 1) {
            d0 += __shfl_xor_sync(0xffffffffu, d0, o);
            d1 += __shfl_xor_sync(0xffffffffu, d1, o);
        }
        float mx = fmaxf(m, fmaxf(d0, d1));
        float sc = __expf(m - mx);
        float q0 = __expf(d0 - mx);
        float q1 = __expf(d1 - mx);
        m = mx;
        den = den * sc + q0 + q1;
#pragma unroll
        for (int j = 0; j < 8; j++)
            acc8[j] = acc8[j] * sc + q0 * xv0[j] + q1 * xv1[j];
    }

    if (i < end) {
        int s = g_srcList[i];
        const float* p0 = g_xl + (size_t)s * HC + colBase;
        float4 u0 = *(const float4*)(p0), u1 = *(const float4*)(p0 + 4);
        float xv[8] = {u0.x,u0.y,u0.z,u0.w,u1.x,u1.y,u1.z,u1.w};
        float d0 = 0.f;
#pragma unroll
        for (int j = 0; j < 8; j++) {
            float e = xv[j] + xr8[j];
            e = (e > 0.f) ? e : NEG_SLOPE * e;
            d0 += e * at8[j];
        }
#pragma unroll
        for (int o = 8; o; o >>= 1)
            d0 += __shfl_xor_sync(0xffffffffu, d0, o);
        float mx = fmaxf(m, d0);
        float sc = __expf(m - mx);
        float q = __expf(d0 - mx);
        m = mx;
        den = den * sc + q;
#pragma unroll
        for (int j = 0; j < 8; j++)
            acc8[j] = acc8[j] * sc + q * xv[j];
    }

    float inv = 1.f / den;
    float* outp = selOut(outext, osel) + (size_t)nd * HC + colBase;
    const float* bp = bias + colBase;
    float4 o0, o1;
    o0.x = acc8[0]*inv + bp[0]; o0.y = acc8[1]*inv + bp[1];
    o0.z = acc8[2]*inv + bp[2]; o0.w = acc8[3]*inv + bp[3];
    o1.x = acc8[4]*inv + bp[4]; o1.y = acc8[5]*inv + bp[5];
    o1.z = acc8[6]*inv + bp[6]; o1.w = acc8[7]*inv + bp[7];
    *(float4*)(outp)     = o0;
    *(float4*)(outp + 4) = o1;
}

// ---------------- fused aggregation, H=1 C=32 (final layer) (R6) -------------
__global__ __launch_bounds__(256) void gat_agg1_kernel(
    const float* __restrict__ att, const float* __restrict__ bias,
    float* outext, int osel)
{
    constexpr int HC = 32;
    int nd = (blockIdx.x * blockDim.x + threadIdx.x) >> 5;
    int lane = threadIdx.x & 31;
    if (nd >= NN) return;

    float xr = g_xr[(size_t)nd * HC + lane];
    float at = att[lane];
    float acc = 0.f, m = -1e30f, den = 0.f;

    int beg = g_ofs[nd];
    int end = (nd == NN - 1) ? ET : g_ofs[nd + 1];
    int i = beg;
    int endPair = beg + ((end - beg) & ~1);

    for (; i < endPair; i += 2) {
        int s0 = g_srcList[i];
        int s1 = g_srcList[i + 1];
        float xv0 = g_xl[(size_t)s0 * HC + lane];
        float xv1 = g_xl[(size_t)s1 * HC + lane];
        float e0 = xv0 + xr; e0 = (e0 > 0.f) ? e0 : NEG_SLOPE * e0;
        float e1 = xv1 + xr; e1 = (e1 > 0.f) ? e1 : NEG_SLOPE * e1;
        float d0 = e0 * at, d1 = e1 * at;
#pragma unroll
        for (int o = 16; o; o >>= 1) {
            d0 += __shfl_xor_sync(0xffffffffu, d0, o);
            d1 += __shfl_xor_sync(0xffffffffu, d1, o);
        }
        float mx = fmaxf(m, fmaxf(d0, d1));
        float sc = __expf(m - mx);
        float q0 = __expf(d0 - mx);
        float q1 = __expf(d1 - mx);
        m = mx;
        den = den * sc + q0 + q1;
        acc = acc * sc + q0 * xv0 + q1 * xv1;
    }
    if (i < end) {
        int s = g_srcList[i];
        float xv = g_xl[(size_t)s * HC + lane];
        float e = xv + xr; e = (e > 0.f) ? e : NEG_SLOPE * e;
        float d0 = e * at;
#pragma unroll
        for (int o = 16; o; o >>= 1)
            d0 += __shfl_xor_sync(0xffffffffu, d0, o);
        float mx = fmaxf(m, d0);
        float sc = __expf(m - mx);
        float q = __expf(d0 - mx);
        m = mx;
        den = den * sc + q;
        acc = acc * sc + q * xv;
    }

    selOut(outext, osel)[(size_t)nd * HC + lane] = acc / den + bias[lane];
}

// ---------------- launch -----------------------------------------------------
extern "C" void kernel_launch(void* const* d_in, const int* in_sizes, int n_in,
                              void* d_out, int out_size)
{
    const float* x  = (const float*)d_in[0];
    const void*  ei = d_in[1];
    const float* Wl[4]   = {(const float*)d_in[2],  (const float*)d_in[6],
                            (const float*)d_in[10], (const float*)d_in[14]};
    const float* Wr[4]   = {(const float*)d_in[3],  (const float*)d_in[7],
                            (const float*)d_in[11], (const float*)d_in[15]};
    const float* att[4]  = {(const float*)d_in[4],  (const float*)d_in[8],
                            (const float*)d_in[12], (const float*)d_in[16]};
    const float* bias[4] = {(const float*)d_in[5],  (const float*)d_in[9],
                            (const float*)d_in[13], (const float*)d_in[17]};
    float* out = (float*)d_out;

    int nb = (NN + 255) / 256;
    int aggBlocks = (NN * 32 + 255) / 256;
    int rowBlocks = (NN + 127) / 128;

    // CSR build (edge_index constant across layers)
    init_csr_kernel<<<nb, 256>>>((const int*)ei);
    count_kernel<<<(ET + 255) / 256, 256>>>(ei);
    scan1_kernel<<<nb, 256>>>();
    scan2_kernel<<<1, 256>>>(nb);
    scan3_kernel<<<nb, 256>>>();
    fill_kernel<<<(ET + 255) / 256, 256>>>(ei);

    const int cfgK[4] = {1024, 256, 256, 256};
    const int inSel[4]  = {0, 1, 2, 1};
    const int outSel[4] = {1, 2, 1, 0};

    for (int l = 0; l < 4; l++) {
        int K = cfgK[l];
        int HC = (l == 3) ? 32 : 256;
        int fusedN = 2 * HC;

        dim3 gg((fusedN + 127) / 128, rowBlocks);
        gemm_tf32<<<gg, 512>>>(x, inSel[l], Wl[l], Wr[l], NN, HC, fusedN, K);

        if (l == 3)
            gat_agg1_kernel<<<aggBlocks, 256>>>(att[l], bias[l], out, outSel[l]);
        else
            gat_agg2_kernel<<<aggBlocks, 256>>>(att[l], bias[l], out, outSel[l]);
    }
}

// round 14
// speedup vs baseline: 1.0509x; 1.0509x over previous
#include <cuda_runtime.h>
#include <cstdint>

#define NN 50000
#define NE 400000
#define ET (NN + NE)
#define NEG_SLOPE 0.2f

// ---------------- scratch (device globals) -----------------------------------
__device__ float g_xl[NN * 256];
__device__ float g_xr[NN * 256];
__device__ float g_hA[NN * 256];
__device__ float g_hB[NN * 256];
__device__ int   g_cnt[NN];
__device__ int   g_ofs[NN];
__device__ int   g_fill[NN];
__device__ int   g_srcList[ET];
__device__ int   g_bsum[256];
__device__ int   g_boff[256];
__device__ int   g_is64;

// ---------------- helpers ----------------------------------------------------
__device__ __forceinline__ const float* selIn(const float* ext, int sel) {
    return sel == 1 ? g_hA : (sel == 2 ? g_hB : ext);
}
__device__ __forceinline__ float* selOut(float* ext, int sel) {
    return sel == 1 ? g_hA : (sel == 2 ? g_hB : ext);
}

// f32 -> tf32 (rna) in register
__device__ __forceinline__ unsigned t32(float f) {
    unsigned u;
    asm("cvt.rna.tf32.f32 %0, %1;" : "=r"(u) : "f"(f));
    return u;
}

__device__ __forceinline__ void cpasync16(const void* smem_dst, const void* gsrc, int sz) {
    unsigned dst = (unsigned)__cvta_generic_to_shared(smem_dst);
    asm volatile("cp.async.cg.shared.global [%0], [%1], 16, %2;"
                 :: "r"(dst), "l"(gsrc), "r"(sz));
}
#define CP_COMMIT() asm volatile("cp.async.commit_group;")
#define CP_WAIT1()  asm volatile("cp.async.wait_group 1;")

// merged: zero g_cnt across grid; block 0 also detects edge_index dtype
__global__ void init_csr_kernel(const int* __restrict__ ei) {
    int i = blockIdx.x * blockDim.x + threadIdx.x;
    if (i < NN) g_cnt[i] = 0;
    if (blockIdx.x == 0 && threadIdx.x == 0) {
        int all0 = 1;
        for (int j = 0; j < 64; j++)
            if (ei[2 * j + 1] != 0) all0 = 0;
        g_is64 = all0;
    }
}

__device__ __forceinline__ void load_edge(const void* ei, int e, int& s, int& d) {
    if (e >= NE) { s = d = e - NE; return; }   // self loops appended at the end
    if (g_is64) {
        const long long* p = (const long long*)ei;
        s = (int)p[e]; d = (int)p[NE + e];
    } else {
        const int* p = (const int*)ei;
        s = p[e]; d = p[NE + e];
    }
}

// ---------------- CSR build ---------------------------------------------------
__global__ void count_kernel(const void* ei) {
    int e = blockIdx.x * blockDim.x + threadIdx.x;
    if (e >= ET) return;
    int s, d; load_edge(ei, e, s, d);
    (void)s;
    atomicAdd(&g_cnt[d], 1);
}

__global__ void scan1_kernel() {
    __shared__ int ws[8];
    int tid = threadIdx.x, lane = tid & 31, wid = tid >> 5;
    int i = blockIdx.x * 256 + tid;
    int v = (i < NN) ? g_cnt[i] : 0;
    int x = v;
#pragma unroll
    for (int o = 1; o < 32; o <<= 1) {
        int y = __shfl_up_sync(0xffffffffu, x, o);
        if (lane >= o) x += y;
    }
    if (lane == 31) ws[wid] = x;
    __syncthreads();
    if (tid == 0) {
        int run = 0;
        for (int j = 0; j < 8; j++) { int t = ws[j]; ws[j] = run; run += t; }
        g_bsum[blockIdx.x] = run;
    }
    __syncthreads();
    if (i < NN) g_ofs[i] = x - v + ws[wid];
}

__global__ void scan2_kernel(int nb) {
    __shared__ int ws[8];
    int tid = threadIdx.x, lane = tid & 31, wid = tid >> 5;
    int v = (tid < nb) ? g_bsum[tid] : 0;
    int x = v;
#pragma unroll
    for (int o = 1; o < 32; o <<= 1) {
        int y = __shfl_up_sync(0xffffffffu, x, o);
        if (lane >= o) x += y;
    }
    if (lane == 31) ws[wid] = x;
    __syncthreads();
    if (tid == 0) {
        int run = 0;
        for (int j = 0; j < 8; j++) { int t = ws[j]; ws[j] = run; run += t; }
    }
    __syncthreads();
    if (tid < nb) g_boff[tid] = x - v + ws[wid];
}

__global__ void scan3_kernel() {
    int i = blockIdx.x * 256 + threadIdx.x;
    if (i >= NN) return;
    int o = g_ofs[i] + g_boff[blockIdx.x];
    g_ofs[i] = o;
    g_fill[i] = o;
}

__global__ void fill_kernel(const void* ei) {
    int e = blockIdx.x * blockDim.x + threadIdx.x;
    if (e >= ET) return;
    int s, d; load_edge(ei, e, s, d);
    int pos = atomicAdd(&g_fill[d], 1);
    g_srcList[pos] = s;
}

// ---------------- tf32 tensor-core GEMM, cp.async 2-stage, K-chunk 32 --------
// Same pipeline scheme as the proven R6 kernel; only the chunk size doubles:
// half the barriers/waits, 2x independent work between them, 2x lookahead.
#define MMA_TF32(d, a, b)                                                      \
    asm volatile(                                                              \
        "mma.sync.aligned.m16n8k8.row.col.f32.tf32.tf32.f32 "                  \
        "{%0,%1,%2,%3}, {%4,%5,%6,%7}, {%8,%9}, {%0,%1,%2,%3};"                \
        : "+f"(d[0]), "+f"(d[1]), "+f"(d[2]), "+f"(d[3])                       \
        : "r"(a[0]), "r"(a[1]), "r"(a[2]), "r"(a[3]), "r"(b[0]), "r"(b[1]))

#define A_ST 4608   // 128 rows * stride 36 floats
#define B_ST 4224   // 32 k * stride 132 floats
#define GEMM_SMEM ((2 * A_ST + 2 * B_ST) * 4)   // 70656 bytes

__global__ __launch_bounds__(256, 2) void gemm_tf32(
    const float* __restrict__ Aext, int asel,
    const float* __restrict__ Wl, const float* __restrict__ Wr,
    int M, int HC, int fusedN, int K)
{
    extern __shared__ float sm[];
    float* AsB = sm;                  // [2][128][36]
    float* BsB = sm + 2 * A_ST;       // [2][32][132]

    const float* A = selIn(Aext, asel);

    int tid = threadIdx.x;
    int lane = tid & 31, warp = tid >> 5;
    int wm = (warp & 1) * 64, wn = (warp >> 1) * 32;
    int rowBase = blockIdx.y * 128, colBase = blockIdx.x * 128;

    float acc[4][4][4];
#pragma unroll
    for (int i = 0; i < 4; i++)
#pragma unroll
        for (int j = 0; j < 4; j++)
#pragma unroll
            for (int q = 0; q < 4; q++) acc[i][j][q] = 0.f;

    // A loader: 2 threads per row, 16 floats (4x 16B) each
    int aRow = tid >> 1, aHalf = (tid & 1) * 16;
    // B loader: thread covers k-rows bRow0 + {0,8,16,24} at 4 cols
    int bRow0 = tid >> 5, bCol = (tid & 31) * 4;

    int gc = colBase + bCol;
    const float* bColBase_ptr;
    int bsz;
    if (gc >= fusedN) { bColBase_ptr = Wl; bsz = 0; }
    else if (gc < HC) { bColBase_ptr = Wl + gc; bsz = 16; }
    else              { bColBase_ptr = Wr + (gc - HC); bsz = 16; }

    int grow = rowBase + aRow;
    const float* aPtr = A + (size_t)min(grow, M - 1) * K + aHalf;
    int asz = (grow < M) ? 16 : 0;

    int nK = K >> 5;

#define ISSUE(kt, buf)                                                          \
    do {                                                                        \
        int k0_ = (kt) << 5;                                                    \
        float* aq = AsB + (buf) * A_ST + aRow * 36 + aHalf;                     \
        const float* ag = aPtr + k0_;                                           \
        cpasync16(aq + 0,  ag + 0,  asz);                                       \
        cpasync16(aq + 4,  ag + 4,  asz);                                       \
        cpasync16(aq + 8,  ag + 8,  asz);                                       \
        cpasync16(aq + 12, ag + 12, asz);                                       \
        float* bq = BsB + (buf) * B_ST;                                         \
        const float* bg = bColBase_ptr;                                         \
        cpasync16(bq + (bRow0 +  0) * 132 + bCol,                               \
                  bg + (size_t)(k0_ + bRow0 +  0) * HC, bsz);                   \
        cpasync16(bq + (bRow0 +  8) * 132 + bCol,                               \
                  bg + (size_t)(k0_ + bRow0 +  8) * HC, bsz);                   \
        cpasync16(bq + (bRow0 + 16) * 132 + bCol,                               \
                  bg + (size_t)(k0_ + bRow0 + 16) * HC, bsz);                   \
        cpasync16(bq + (bRow0 + 24) * 132 + bCol,                               \
                  bg + (size_t)(k0_ + bRow0 + 24) * HC, bsz);                   \
    } while (0)

    ISSUE(0, 0);
    CP_COMMIT();

    int buf = 0;
    int r = lane >> 2, c = lane & 3;

    for (int kt = 0; kt < nK; kt++) {
        if (kt + 1 < nK) ISSUE(kt + 1, buf ^ 1);
        CP_COMMIT();
        CP_WAIT1();
        __syncthreads();

        const float* aq = AsB + buf * A_ST;
        const float* bq = BsB + buf * B_ST;
#pragma unroll
        for (int ks = 0; ks < 4; ks++) {
            int kk = ks * 8;
            unsigned a[4][4], b[4][2];
#pragma unroll
            for (int mi = 0; mi < 4; mi++) {
                int rb = wm + mi * 16 + r;
                a[mi][0] = t32(aq[rb * 36 + kk + c]);
                a[mi][1] = t32(aq[(rb + 8) * 36 + kk + c]);
                a[mi][2] = t32(aq[rb * 36 + kk + c + 4]);
                a[mi][3] = t32(aq[(rb + 8) * 36 + kk + c + 4]);
            }
#pragma unroll
            for (int ni = 0; ni < 4; ni++) {
                int nb = wn + ni * 8 + r;
                b[ni][0] = t32(bq[(kk + c) * 132 + nb]);
                b[ni][1] = t32(bq[(kk + c + 4) * 132 + nb]);
            }
#pragma unroll
            for (int mi = 0; mi < 4; mi++)
#pragma unroll
                for (int ni = 0; ni < 4; ni++)
                    MMA_TF32(acc[mi][ni], a[mi], b[ni]);
        }
        __syncthreads();
        buf ^= 1;
    }
#undef ISSUE

    // ---- epilogue: route columns to g_xl / g_xr
    int c2 = (lane & 3) * 2;
#pragma unroll
    for (int mi = 0; mi < 4; mi++) {
#pragma unroll
        for (int ni = 0; ni < 4; ni++) {
            int col = colBase + wn + ni * 8 + c2;
            if (col >= fusedN) continue;
            float* base; int cc;
            if (col < HC) { base = g_xl; cc = col; }
            else          { base = g_xr; cc = col - HC; }
#pragma unroll
            for (int half = 0; half < 2; half++) {
                int row = rowBase + wm + mi * 16 + r + half * 8;
                if (row < M) {
                    *(float2*)(base + (size_t)row * HC + cc) =
                        make_float2(acc[mi][ni][half * 2],
                                    acc[mi][ni][half * 2 + 1]);
                }
            }
        }
    }
}

// ---------------- fused aggregation, H=2 C=128, head-split lanes (R6) --------
__global__ __launch_bounds__(256) void gat_agg2_kernel(
    const float* __restrict__ att, const float* __restrict__ bias,
    float* outext, int osel)
{
    constexpr int HC = 256;
    int nd = (blockIdx.x * blockDim.x + threadIdx.x) >> 5;
    int lane = threadIdx.x & 31;
    if (nd >= NN) return;

    int colBase = (lane >> 4) * 128 + (lane & 15) * 8;

    float xr8[8], at8[8], acc8[8];
    {
        const float* xrp = g_xr + (size_t)nd * HC + colBase;
        const float* atp = att + colBase;
        float4 xa = *(const float4*)(xrp), xb = *(const float4*)(xrp + 4);
        float4 aa = *(const float4*)(atp), ab = *(const float4*)(atp + 4);
        xr8[0]=xa.x; xr8[1]=xa.y; xr8[2]=xa.z; xr8[3]=xa.w;
        xr8[4]=xb.x; xr8[5]=xb.y; xr8[6]=xb.z; xr8[7]=xb.w;
        at8[0]=aa.x; at8[1]=aa.y; at8[2]=aa.z; at8[3]=aa.w;
        at8[4]=ab.x; at8[5]=ab.y; at8[6]=ab.z; at8[7]=ab.w;
#pragma unroll
        for (int j = 0; j < 8; j++) acc8[j] = 0.f;
    }
    float m = -1e30f, den = 0.f;

    int beg = g_ofs[nd];
    int end = (nd == NN - 1) ? ET : g_ofs[nd + 1];
    int i = beg;
    int endPair = beg + ((end - beg) & ~1);

    for (; i < endPair; i += 2) {
        int s0 = g_srcList[i];
        int s1 = g_srcList[i + 1];
        const float* p0 = g_xl + (size_t)s0 * HC + colBase;
        const float* p1 = g_xl + (size_t)s1 * HC + colBase;

        float4 u0 = *(const float4*)(p0), u1 = *(const float4*)(p0 + 4);
        float4 v0 = *(const float4*)(p1), v1 = *(const float4*)(p1 + 4);
        float xv0[8] = {u0.x,u0.y,u0.z,u0.w,u1.x,u1.y,u1.z,u1.w};
        float xv1[8] = {v0.x,v0.y,v0.z,v0.w,v1.x,v1.y,v1.z,v1.w};

        float d0 = 0.f, d1 = 0.f;
#pragma unroll
        for (int j = 0; j < 8; j++) {
            float e0 = xv0[j] + xr8[j];
            float e1 = xv1[j] + xr8[j];
            e0 = (e0 > 0.f) ? e0 : NEG_SLOPE * e0;
            e1 = (e1 > 0.f) ? e1 : NEG_SLOPE * e1;
            d0 += e0 * at8[j];
            d1 += e1 * at8[j];
        }
#pragma unroll
        for (int o = 8; o; o >>= 1) {
            d0 += __shfl_xor_sync(0xffffffffu, d0, o);
            d1 += __shfl_xor_sync(0xffffffffu, d1, o);
        }
        float mx = fmaxf(m, fmaxf(d0, d1));
        float sc = __expf(m - mx);
        float q0 = __expf(d0 - mx);
        float q1 = __expf(d1 - mx);
        m = mx;
        den = den * sc + q0 + q1;
#pragma unroll
        for (int j = 0; j < 8; j++)
            acc8[j] = acc8[j] * sc + q0 * xv0[j] + q1 * xv1[j];
    }

    if (i < end) {
        int s = g_srcList[i];
        const float* p0 = g_xl + (size_t)s * HC + colBase;
        float4 u0 = *(const float4*)(p0), u1 = *(const float4*)(p0 + 4);
        float xv[8] = {u0.x,u0.y,u0.z,u0.w,u1.x,u1.y,u1.z,u1.w};
        float d0 = 0.f;
#pragma unroll
        for (int j = 0; j < 8; j++) {
            float e = xv[j] + xr8[j];
            e = (e > 0.f) ? e : NEG_SLOPE * e;
            d0 += e * at8[j];
        }
#pragma unroll
        for (int o = 8; o; o >>= 1)
            d0 += __shfl_xor_sync(0xffffffffu, d0, o);
        float mx = fmaxf(m, d0);
        float sc = __expf(m - mx);
        float q = __expf(d0 - mx);
        m = mx;
        den = den * sc + q;
#pragma unroll
        for (int j = 0; j < 8; j++)
            acc8[j] = acc8[j] * sc + q * xv[j];
    }

    float inv = 1.f / den;
    float* outp = selOut(outext, osel) + (size_t)nd * HC + colBase;
    const float* bp = bias + colBase;
    float4 o0, o1;
    o0.x = acc8[0]*inv + bp[0]; o0.y = acc8[1]*inv + bp[1];
    o0.z = acc8[2]*inv + bp[2]; o0.w = acc8[3]*inv + bp[3];
    o1.x = acc8[4]*inv + bp[4]; o1.y = acc8[5]*inv + bp[5];
    o1.z = acc8[6]*inv + bp[6]; o1.w = acc8[7]*inv + bp[7];
    *(float4*)(outp)     = o0;
    *(float4*)(outp + 4) = o1;
}

// ---------------- fused aggregation, H=1 C=32 (final layer) (R6) -------------
__global__ __launch_bounds__(256) void gat_agg1_kernel(
    const float* __restrict__ att, const float* __restrict__ bias,
    float* outext, int osel)
{
    constexpr int HC = 32;
    int nd = (blockIdx.x * blockDim.x + threadIdx.x) >> 5;
    int lane = threadIdx.x & 31;
    if (nd >= NN) return;

    float xr = g_xr[(size_t)nd * HC + lane];
    float at = att[lane];
    float acc = 0.f, m = -1e30f, den = 0.f;

    int beg = g_ofs[nd];
    int end = (nd == NN - 1) ? ET : g_ofs[nd + 1];
    int i = beg;
    int endPair = beg + ((end - beg) & ~1);

    for (; i < endPair; i += 2) {
        int s0 = g_srcList[i];
        int s1 = g_srcList[i + 1];
        float xv0 = g_xl[(size_t)s0 * HC + lane];
        float xv1 = g_xl[(size_t)s1 * HC + lane];
        float e0 = xv0 + xr; e0 = (e0 > 0.f) ? e0 : NEG_SLOPE * e0;
        float e1 = xv1 + xr; e1 = (e1 > 0.f) ? e1 : NEG_SLOPE * e1;
        float d0 = e0 * at, d1 = e1 * at;
#pragma unroll
        for (int o = 16; o; o >>= 1) {
            d0 += __shfl_xor_sync(0xffffffffu, d0, o);
            d1 += __shfl_xor_sync(0xffffffffu, d1, o);
        }
        float mx = fmaxf(m, fmaxf(d0, d1));
        float sc = __expf(m - mx);
        float q0 = __expf(d0 - mx);
        float q1 = __expf(d1 - mx);
        m = mx;
        den = den * sc + q0 + q1;
        acc = acc * sc + q0 * xv0 + q1 * xv1;
    }
    if (i < end) {
        int s = g_srcList[i];
        float xv = g_xl[(size_t)s * HC + lane];
        float e = xv + xr; e = (e > 0.f) ? e : NEG_SLOPE * e;
        float d0 = e * at;
#pragma unroll
        for (int o = 16; o; o >>= 1)
            d0 += __shfl_xor_sync(0xffffffffu, d0, o);
        float mx = fmaxf(m, d0);
        float sc = __expf(m - mx);
        float q = __expf(d0 - mx);
        m = mx;
        den = den * sc + q;
        acc = acc * sc + q * xv;
    }

    selOut(outext, osel)[(size_t)nd * HC + lane] = acc / den + bias[lane];
}

// ---------------- launch -----------------------------------------------------
extern "C" void kernel_launch(void* const* d_in, const int* in_sizes, int n_in,
                              void* d_out, int out_size)
{
    const float* x  = (const float*)d_in[0];
    const void*  ei = d_in[1];
    const float* Wl[4]   = {(const float*)d_in[2],  (const float*)d_in[6],
                            (const float*)d_in[10], (const float*)d_in[14]};
    const float* Wr[4]   = {(const float*)d_in[3],  (const float*)d_in[7],
                            (const float*)d_in[11], (const float*)d_in[15]};
    const float* att[4]  = {(const float*)d_in[4],  (const float*)d_in[8],
                            (const float*)d_in[12], (const float*)d_in[16]};
    const float* bias[4] = {(const float*)d_in[5],  (const float*)d_in[9],
                            (const float*)d_in[13], (const float*)d_in[17]};
    float* out = (float*)d_out;

    cudaFuncSetAttribute(gemm_tf32,
                         cudaFuncAttributeMaxDynamicSharedMemorySize, GEMM_SMEM);

    int nb = (NN + 255) / 256;
    int aggBlocks = (NN * 32 + 255) / 256;
    int rowBlocks = (NN + 127) / 128;

    // CSR build (edge_index constant across layers)
    init_csr_kernel<<<nb, 256>>>((const int*)ei);
    count_kernel<<<(ET + 255) / 256, 256>>>(ei);
    scan1_kernel<<<nb, 256>>>();
    scan2_kernel<<<1, 256>>>(nb);
    scan3_kernel<<<nb, 256>>>();
    fill_kernel<<<(ET + 255) / 256, 256>>>(ei);

    const int cfgK[4] = {1024, 256, 256, 256};
    const int inSel[4]  = {0, 1, 2, 1};
    const int outSel[4] = {1, 2, 1, 0};

    for (int l = 0; l < 4; l++) {
        int K = cfgK[l];
        int HC = (l == 3) ? 32 : 256;
        int fusedN = 2 * HC;

        dim3 gg((fusedN + 127) / 128, rowBlocks);
        gemm_tf32<<<gg, 256, GEMM_SMEM>>>(x, inSel[l], Wl[l], Wr[l],
                                          NN, HC, fusedN, K);

        if (l == 3)
            gat_agg1_kernel<<<aggBlocks, 256>>>(att[l], bias[l], out, outSel[l]);
        else
            gat_agg2_kernel<<<aggBlocks, 256>>>(att[l], bias[l], out, outSel[l]);
    }
}

// round 15
// speedup vs baseline: 1.2241x; 1.1648x over previous
#include <cuda_runtime.h>
#include <cstdint>

#define NN 50000
#define NE 400000
#define ET (NN + NE)
#define NEG_SLOPE 0.2f

// ---------------- scratch (device globals) -----------------------------------
__device__ float g_xl[NN * 256];
__device__ float g_xr[NN * 256];
__device__ float g_hA[NN * 256];
__device__ float g_hB[NN * 256];
__device__ int   g_cnt[NN];
__device__ int   g_ofs[NN];
__device__ int   g_fill[NN];
__device__ int   g_srcList[ET];
__device__ int   g_bsum[256];
__device__ int   g_boff[256];
__device__ int   g_is64;

// ---------------- helpers ----------------------------------------------------
__device__ __forceinline__ const float* selIn(const float* ext, int sel) {
    return sel == 1 ? g_hA : (sel == 2 ? g_hB : ext);
}
__device__ __forceinline__ float* selOut(float* ext, int sel) {
    return sel == 1 ? g_hA : (sel == 2 ? g_hB : ext);
}

// f32 -> tf32 (rna) in register
__device__ __forceinline__ unsigned t32(float f) {
    unsigned u;
    asm("cvt.rna.tf32.f32 %0, %1;" : "=r"(u) : "f"(f));
    return u;
}

__device__ __forceinline__ void cpasync16(const void* smem_dst, const void* gsrc, int sz) {
    unsigned dst = (unsigned)__cvta_generic_to_shared(smem_dst);
    asm volatile("cp.async.cg.shared.global [%0], [%1], 16, %2;"
                 :: "r"(dst), "l"(gsrc), "r"(sz));
}
#define CP_COMMIT() asm volatile("cp.async.commit_group;")
#define CP_WAIT1()  asm volatile("cp.async.wait_group 1;")

// merged: zero g_cnt across grid; block 0 also detects edge_index dtype
__global__ void init_csr_kernel(const int* __restrict__ ei) {
    int i = blockIdx.x * blockDim.x + threadIdx.x;
    if (i < NN) g_cnt[i] = 0;
    if (blockIdx.x == 0 && threadIdx.x == 0) {
        int all0 = 1;
        for (int j = 0; j < 64; j++)
            if (ei[2 * j + 1] != 0) all0 = 0;
        g_is64 = all0;
    }
}

__device__ __forceinline__ void load_edge(const void* ei, int e, int& s, int& d) {
    if (e >= NE) { s = d = e - NE; return; }   // self loops appended at the end
    if (g_is64) {
        const long long* p = (const long long*)ei;
        s = (int)p[e]; d = (int)p[NE + e];
    } else {
        const int* p = (const int*)ei;
        s = p[e]; d = p[NE + e];
    }
}

// ---------------- CSR build ---------------------------------------------------
__global__ void count_kernel(const void* ei) {
    int e = blockIdx.x * blockDim.x + threadIdx.x;
    if (e >= ET) return;
    int s, d; load_edge(ei, e, s, d);
    (void)s;
    atomicAdd(&g_cnt[d], 1);
}

__global__ void scan1_kernel() {
    __shared__ int ws[8];
    int tid = threadIdx.x, lane = tid & 31, wid = tid >> 5;
    int i = blockIdx.x * 256 + tid;
    int v = (i < NN) ? g_cnt[i] : 0;
    int x = v;
#pragma unroll
    for (int o = 1; o < 32; o <<= 1) {
        int y = __shfl_up_sync(0xffffffffu, x, o);
        if (lane >= o) x += y;
    }
    if (lane == 31) ws[wid] = x;
    __syncthreads();
    if (tid == 0) {
        int run = 0;
        for (int j = 0; j < 8; j++) { int t = ws[j]; ws[j] = run; run += t; }
        g_bsum[blockIdx.x] = run;
    }
    __syncthreads();
    if (i < NN) g_ofs[i] = x - v + ws[wid];
}

__global__ void scan2_kernel(int nb) {
    __shared__ int ws[8];
    int tid = threadIdx.x, lane = tid & 31, wid = tid >> 5;
    int v = (tid < nb) ? g_bsum[tid] : 0;
    int x = v;
#pragma unroll
    for (int o = 1; o < 32; o <<= 1) {
        int y = __shfl_up_sync(0xffffffffu, x, o);
        if (lane >= o) x += y;
    }
    if (lane == 31) ws[wid] = x;
    __syncthreads();
    if (tid == 0) {
        int run = 0;
        for (int j = 0; j < 8; j++) { int t = ws[j]; ws[j] = run; run += t; }
    }
    __syncthreads();
    if (tid < nb) g_boff[tid] = x - v + ws[wid];
}

__global__ void scan3_kernel() {
    int i = blockIdx.x * 256 + threadIdx.x;
    if (i >= NN) return;
    int o = g_ofs[i] + g_boff[blockIdx.x];
    g_ofs[i] = o;
    g_fill[i] = o;
}

__global__ void fill_kernel(const void* ei) {
    int e = blockIdx.x * blockDim.x + threadIdx.x;
    if (e >= ET) return;
    int s, d; load_edge(ei, e, s, d);
    int pos = atomicAdd(&g_fill[d], 1);
    g_srcList[pos] = s;
}

// ---------------- tf32 tensor-core GEMM (R6 + B bank-conflict fix) -----------
// [xl | xr] = A[M,K] @ [Wl | Wr], block 128x128, K-step 16, 2 stages.
// Bs stride 136 (mod 32 == 8): B fragment banks = 8c + r, all 32 distinct.
// (Old stride 132 gave 2-way conflicts on 24/32 lanes.)
#define MMA_TF32(d, a, b)                                                      \
    asm volatile(                                                              \
        "mma.sync.aligned.m16n8k8.row.col.f32.tf32.tf32.f32 "                  \
        "{%0,%1,%2,%3}, {%4,%5,%6,%7}, {%8,%9}, {%0,%1,%2,%3};"                \
        : "+f"(d[0]), "+f"(d[1]), "+f"(d[2]), "+f"(d[3])                       \
        : "r"(a[0]), "r"(a[1]), "r"(a[2]), "r"(a[3]), "r"(b[0]), "r"(b[1]))

__global__ __launch_bounds__(256, 2) void gemm_tf32(
    const float* __restrict__ Aext, int asel,
    const float* __restrict__ Wl, const float* __restrict__ Wr,
    int M, int HC, int fusedN, int K)
{
    __shared__ float As[2][128][20];   // 128 rows x 16 k (banks 20r+c: clean)
    __shared__ float Bs[2][16][136];   // 16 k x 128 cols (banks 8c+r: clean)

    const float* A = selIn(Aext, asel);

    int tid = threadIdx.x;
    int lane = tid & 31, warp = tid >> 5;
    int wm = (warp & 1) * 64, wn = (warp >> 1) * 32;
    int rowBase = blockIdx.y * 128, colBase = blockIdx.x * 128;

    float acc[4][4][4];
#pragma unroll
    for (int i = 0; i < 4; i++)
#pragma unroll
        for (int j = 0; j < 4; j++)
#pragma unroll
            for (int q = 0; q < 4; q++) acc[i][j][q] = 0.f;

    int aRow0 = tid >> 2, aCol = (tid & 3) * 4;
    int bRow0 = tid >> 5, bCol = (tid & 31) * 4;

    int gc = colBase + bCol;
    const float* bColBase_ptr;
    int bsz;
    if (gc >= fusedN) { bColBase_ptr = Wl; bsz = 0; }
    else if (gc < HC) { bColBase_ptr = Wl + gc; bsz = 16; }
    else              { bColBase_ptr = Wr + (gc - HC); bsz = 16; }

    int gr0 = rowBase + aRow0, gr1 = rowBase + aRow0 + 64;
    const float* aPtr0 = A + (size_t)min(gr0, M - 1) * K + aCol;
    const float* aPtr1 = A + (size_t)min(gr1, M - 1) * K + aCol;
    int asz0 = (gr0 < M) ? 16 : 0;
    int asz1 = (gr1 < M) ? 16 : 0;

    int nK = K >> 4;

#define ISSUE(kt, buf)                                                          \
    do {                                                                        \
        int k0_ = (kt) << 4;                                                    \
        cpasync16(&As[buf][aRow0][aCol],      aPtr0 + k0_, asz0);               \
        cpasync16(&As[buf][aRow0 + 64][aCol], aPtr1 + k0_, asz1);               \
        cpasync16(&Bs[buf][bRow0][bCol],                                        \
                  bColBase_ptr + (size_t)(k0_ + bRow0) * HC, bsz);              \
        cpasync16(&Bs[buf][bRow0 + 8][bCol],                                    \
                  bColBase_ptr + (size_t)(k0_ + bRow0 + 8) * HC, bsz);          \
    } while (0)

    ISSUE(0, 0);
    CP_COMMIT();

    int buf = 0;
    int r = lane >> 2, c = lane & 3;

    for (int kt = 0; kt < nK; kt++) {
        if (kt + 1 < nK) ISSUE(kt + 1, buf ^ 1);
        CP_COMMIT();
        CP_WAIT1();
        __syncthreads();

#pragma unroll
        for (int ks = 0; ks < 2; ks++) {
            int kk = ks * 8;
            unsigned a[4][4], b[4][2];
#pragma unroll
            for (int mi = 0; mi < 4; mi++) {
                int rb = wm + mi * 16 + r;
                a[mi][0] = t32(As[buf][rb][kk + c]);
                a[mi][1] = t32(As[buf][rb + 8][kk + c]);
                a[mi][2] = t32(As[buf][rb][kk + c + 4]);
                a[mi][3] = t32(As[buf][rb + 8][kk + c + 4]);
            }
#pragma unroll
            for (int ni = 0; ni < 4; ni++) {
                int nb = wn + ni * 8 + r;
                b[ni][0] = t32(Bs[buf][kk + c][nb]);
                b[ni][1] = t32(Bs[buf][kk + c + 4][nb]);
            }
#pragma unroll
            for (int mi = 0; mi < 4; mi++)
#pragma unroll
                for (int ni = 0; ni < 4; ni++)
                    MMA_TF32(acc[mi][ni], a[mi], b[ni]);
        }
        __syncthreads();
        buf ^= 1;
    }
#undef ISSUE

    // ---- epilogue: route columns to g_xl / g_xr
    int c2 = (lane & 3) * 2;
#pragma unroll
    for (int mi = 0; mi < 4; mi++) {
#pragma unroll
        for (int ni = 0; ni < 4; ni++) {
            int col = colBase + wn + ni * 8 + c2;
            if (col >= fusedN) continue;
            float* base; int cc;
            if (col < HC) { base = g_xl; cc = col; }
            else          { base = g_xr; cc = col - HC; }
#pragma unroll
            for (int half = 0; half < 2; half++) {
                int row = rowBase + wm + mi * 16 + r + half * 8;
                if (row < M) {
                    *(float2*)(base + (size_t)row * HC + cc) =
                        make_float2(acc[mi][ni][half * 2],
                                    acc[mi][ni][half * 2 + 1]);
                }
            }
        }
    }
}

// ---------------- fused aggregation, H=2 C=128, head-split lanes (R6) --------
__global__ __launch_bounds__(256) void gat_agg2_kernel(
    const float* __restrict__ att, const float* __restrict__ bias,
    float* outext, int osel)
{
    constexpr int HC = 256;
    int nd = (blockIdx.x * blockDim.x + threadIdx.x) >> 5;
    int lane = threadIdx.x & 31;
    if (nd >= NN) return;

    int colBase = (lane >> 4) * 128 + (lane & 15) * 8;

    float xr8[8], at8[8], acc8[8];
    {
        const float* xrp = g_xr + (size_t)nd * HC + colBase;
        const float* atp = att + colBase;
        float4 xa = *(const float4*)(xrp), xb = *(const float4*)(xrp + 4);
        float4 aa = *(const float4*)(atp), ab = *(const float4*)(atp + 4);
        xr8[0]=xa.x; xr8[1]=xa.y; xr8[2]=xa.z; xr8[3]=xa.w;
        xr8[4]=xb.x; xr8[5]=xb.y; xr8[6]=xb.z; xr8[7]=xb.w;
        at8[0]=aa.x; at8[1]=aa.y; at8[2]=aa.z; at8[3]=aa.w;
        at8[4]=ab.x; at8[5]=ab.y; at8[6]=ab.z; at8[7]=ab.w;
#pragma unroll
        for (int j = 0; j < 8; j++) acc8[j] = 0.f;
    }
    float m = -1e30f, den = 0.f;

    int beg = g_ofs[nd];
    int end = (nd == NN - 1) ? ET : g_ofs[nd + 1];
    int i = beg;
    int endPair = beg + ((end - beg) & ~1);

    for (; i < endPair; i += 2) {
        int s0 = g_srcList[i];
        int s1 = g_srcList[i + 1];
        const float* p0 = g_xl + (size_t)s0 * HC + colBase;
        const float* p1 = g_xl + (size_t)s1 * HC + colBase;

        float4 u0 = *(const float4*)(p0), u1 = *(const float4*)(p0 + 4);
        float4 v0 = *(const float4*)(p1), v1 = *(const float4*)(p1 + 4);
        float xv0[8] = {u0.x,u0.y,u0.z,u0.w,u1.x,u1.y,u1.z,u1.w};
        float xv1[8] = {v0.x,v0.y,v0.z,v0.w,v1.x,v1.y,v1.z,v1.w};

        float d0 = 0.f, d1 = 0.f;
#pragma unroll
        for (int j = 0; j < 8; j++) {
            float e0 = xv0[j] + xr8[j];
            float e1 = xv1[j] + xr8[j];
            e0 = (e0 > 0.f) ? e0 : NEG_SLOPE * e0;
            e1 = (e1 > 0.f) ? e1 : NEG_SLOPE * e1;
            d0 += e0 * at8[j];
            d1 += e1 * at8[j];
        }
#pragma unroll
        for (int o = 8; o; o >>= 1) {
            d0 += __shfl_xor_sync(0xffffffffu, d0, o);
            d1 += __shfl_xor_sync(0xffffffffu, d1, o);
        }
        float mx = fmaxf(m, fmaxf(d0, d1));
        float sc = __expf(m - mx);
        float q0 = __expf(d0 - mx);
        float q1 = __expf(d1 - mx);
        m = mx;
        den = den * sc + q0 + q1;
#pragma unroll
        for (int j = 0; j < 8; j++)
            acc8[j] = acc8[j] * sc + q0 * xv0[j] + q1 * xv1[j];
    }

    if (i < end) {
        int s = g_srcList[i];
        const float* p0 = g_xl + (size_t)s * HC + colBase;
        float4 u0 = *(const float4*)(p0), u1 = *(const float4*)(p0 + 4);
        float xv[8] = {u0.x,u0.y,u0.z,u0.w,u1.x,u1.y,u1.z,u1.w};
        float d0 = 0.f;
#pragma unroll
        for (int j = 0; j < 8; j++) {
            float e = xv[j] + xr8[j];
            e = (e > 0.f) ? e : NEG_SLOPE * e;
            d0 += e * at8[j];
        }
#pragma unroll
        for (int o = 8; o; o >>= 1)
            d0 += __shfl_xor_sync(0xffffffffu, d0, o);
        float mx = fmaxf(m, d0);
        float sc = __expf(m - mx);
        float q = __expf(d0 - mx);
        m = mx;
        den = den * sc + q;
#pragma unroll
        for (int j = 0; j < 8; j++)
            acc8[j] = acc8[j] * sc + q * xv[j];
    }

    float inv = 1.f / den;
    float* outp = selOut(outext, osel) + (size_t)nd * HC + colBase;
    const float* bp = bias + colBase;
    float4 o0, o1;
    o0.x = acc8[0]*inv + bp[0]; o0.y = acc8[1]*inv + bp[1];
    o0.z = acc8[2]*inv + bp[2]; o0.w = acc8[3]*inv + bp[3];
    o1.x = acc8[4]*inv + bp[4]; o1.y = acc8[5]*inv + bp[5];
    o1.z = acc8[6]*inv + bp[6]; o1.w = acc8[7]*inv + bp[7];
    *(float4*)(outp)     = o0;
    *(float4*)(outp + 4) = o1;
}

// ---------------- fused aggregation, H=1 C=32 (final layer) (R6) -------------
__global__ __launch_bounds__(256) void gat_agg1_kernel(
    const float* __restrict__ att, const float* __restrict__ bias,
    float* outext, int osel)
{
    constexpr int HC = 32;
    int nd = (blockIdx.x * blockDim.x + threadIdx.x) >> 5;
    int lane = threadIdx.x & 31;
    if (nd >= NN) return;

    float xr = g_xr[(size_t)nd * HC + lane];
    float at = att[lane];
    float acc = 0.f, m = -1e30f, den = 0.f;

    int beg = g_ofs[nd];
    int end = (nd == NN - 1) ? ET : g_ofs[nd + 1];
    int i = beg;
    int endPair = beg + ((end - beg) & ~1);

    for (; i < endPair; i += 2) {
        int s0 = g_srcList[i];
        int s1 = g_srcList[i + 1];
        float xv0 = g_xl[(size_t)s0 * HC + lane];
        float xv1 = g_xl[(size_t)s1 * HC + lane];
        float e0 = xv0 + xr; e0 = (e0 > 0.f) ? e0 : NEG_SLOPE * e0;
        float e1 = xv1 + xr; e1 = (e1 > 0.f) ? e1 : NEG_SLOPE * e1;
        float d0 = e0 * at, d1 = e1 * at;
#pragma unroll
        for (int o = 16; o; o >>= 1) {
            d0 += __shfl_xor_sync(0xffffffffu, d0, o);
            d1 += __shfl_xor_sync(0xffffffffu, d1, o);
        }
        float mx = fmaxf(m, fmaxf(d0, d1));
        float sc = __expf(m - mx);
        float q0 = __expf(d0 - mx);
        float q1 = __expf(d1 - mx);
        m = mx;
        den = den * sc + q0 + q1;
        acc = acc * sc + q0 * xv0 + q1 * xv1;
    }
    if (i < end) {
        int s = g_srcList[i];
        float xv = g_xl[(size_t)s * HC + lane];
        float e = xv + xr; e = (e > 0.f) ? e : NEG_SLOPE * e;
        float d0 = e * at;
#pragma unroll
        for (int o = 16; o; o >>= 1)
            d0 += __shfl_xor_sync(0xffffffffu, d0, o);
        float mx = fmaxf(m, d0);
        float sc = __expf(m - mx);
        float q = __expf(d0 - mx);
        m = mx;
        den = den * sc + q;
        acc = acc * sc + q * xv;
    }

    selOut(outext, osel)[(size_t)nd * HC + lane] = acc / den + bias[lane];
}

// ---------------- launch -----------------------------------------------------
extern "C" void kernel_launch(void* const* d_in, const int* in_sizes, int n_in,
                              void* d_out, int out_size)
{
    const float* x  = (const float*)d_in[0];
    const void*  ei = d_in[1];
    const float* Wl[4]   = {(const float*)d_in[2],  (const float*)d_in[6],
                            (const float*)d_in[10], (const float*)d_in[14]};
    const float* Wr[4]   = {(const float*)d_in[3],  (const float*)d_in[7],
                            (const float*)d_in[11], (const float*)d_in[15]};
    const float* att[4]  = {(const float*)d_in[4],  (const float*)d_in[8],
                            (const float*)d_in[12], (const float*)d_in[16]};
    const float* bias[4] = {(const float*)d_in[5],  (const float*)d_in[9],
                            (const float*)d_in[13], (const float*)d_in[17]};
    float* out = (float*)d_out;

    int nb = (NN + 255) / 256;
    int aggBlocks = (NN * 32 + 255) / 256;
    int rowBlocks = (NN + 127) / 128;

    // CSR build (edge_index constant across layers)
    init_csr_kernel<<<nb, 256>>>((const int*)ei);
    count_kernel<<<(ET + 255) / 256, 256>>>(ei);
    scan1_kernel<<<nb, 256>>>();
    scan2_kernel<<<1, 256>>>(nb);
    scan3_kernel<<<nb, 256>>>();
    fill_kernel<<<(ET + 255) / 256, 256>>>(ei);

    const int cfgK[4] = {1024, 256, 256, 256};
    const int inSel[4]  = {0, 1, 2, 1};
    const int outSel[4] = {1, 2, 1, 0};

    for (int l = 0; l < 4; l++) {
        int K = cfgK[l];
        int HC = (l == 3) ? 32 : 256;
        int fusedN = 2 * HC;

        dim3 gg((fusedN + 127) / 128, rowBlocks);
        gemm_tf32<<<gg, 256>>>(x, inSel[l], Wl[l], Wr[l], NN, HC, fusedN, K);

        if (l == 3)
            gat_agg1_kernel<<<aggBlocks, 256>>>(att[l], bias[l], out, outSel[l]);
        else
            gat_agg2_kernel<<<aggBlocks, 256>>>(att[l], bias[l], out, outSel[l]);
    }
}